// round 4
// baseline (speedup 1.0000x reference)
#include <cuda_runtime.h>
#include <math.h>

// Problem constants (fixed by the dataset)
#define D     512
#define BLK   64
#define B     128
#define KMAX  64
#define MMAX  7168   // M = 6304 in dataset; margin for safety

// ---------------- scratch (no allocations allowed) ----------------
__device__ float g_cos[B * MMAX];     // cosine similarity [B, M]
__device__ float g_qn[B];             // query norms
__device__ float g_mn[MMAX];          // memory-context norms
__device__ int   g_idx[B * KMAX];     // top-k block indices
__device__ float g_w[B * KMAX];       // softmax weights

// ---------------- row L2 norms (clamped at eps) ----------------
__global__ void norm_kernel(const float* __restrict__ x, float* __restrict__ out, int nrows) {
    int row = blockIdx.x;
    if (row >= nrows) return;
    const float* p = x + (long)row * D;
    int t = threadIdx.x;
    float4 v = *reinterpret_cast<const float4*>(p + t * 4);
    float s = v.x * v.x + v.y * v.y + v.z * v.z + v.w * v.w;
    for (int off = 16; off > 0; off >>= 1) s += __shfl_down_sync(0xffffffffu, s, off);
    __shared__ float ws[4];
    if ((t & 31) == 0) ws[t >> 5] = s;
    __syncthreads();
    if (t == 0) {
        float tot = ws[0] + ws[1] + ws[2] + ws[3];
        out[row] = fmaxf(sqrtf(tot), 1e-8f);
    }
}

// ---------------- cos_sim GEMM: [B,D] x [M,D]^T -> [B,M], tiled 16x16 ----------------
__global__ void cos_kernel(const float* __restrict__ q, const float* __restrict__ m,
                           const float* __restrict__ qn, const float* __restrict__ mn,
                           float* __restrict__ out, int M) {
    __shared__ float As[16][17];
    __shared__ float Bs[16][17];
    int tx = threadIdx.x, ty = threadIdx.y;
    int brow = blockIdx.y * 16;             // batch tile base
    int mrow = blockIdx.x * 16;             // memory tile base
    float acc = 0.f;
    for (int k0 = 0; k0 < D; k0 += 16) {
        As[ty][tx] = q[(long)(brow + ty) * D + k0 + tx];
        int mr = mrow + ty;
        Bs[ty][tx] = (mr < M) ? m[(long)mr * D + k0 + tx] : 0.f;
        __syncthreads();
        #pragma unroll
        for (int kk = 0; kk < 16; kk++)
            acc += As[ty][kk] * Bs[tx][kk];
        __syncthreads();
    }
    int gm = mrow + tx;
    int gb = brow + ty;
    if (gm < M)
        out[(long)gb * M + gm] = acc / (qn[gb] * mn[gm]);
}

// ---------------- top-k + softmax: one block per batch row ----------------
__global__ void topk_kernel(const float* __restrict__ cosim, const int* __restrict__ kptr,
                            int M, int* __restrict__ out_idx, float* __restrict__ out_w) {
    extern __shared__ float row[];               // M floats
    __shared__ float rmax[256];
    __shared__ int   rarg[256];
    __shared__ float vals[KMAX];
    __shared__ int   idxs[KMAX];
    int b = blockIdx.x, t = threadIdx.x;
    int k = *kptr;
    if (k > KMAX) k = KMAX;
    for (int i = t; i < M; i += 256) row[i] = cosim[(long)b * M + i];
    __syncthreads();
    for (int it = 0; it < k; it++) {
        float best = -INFINITY; int barg = 0;
        for (int i = t; i < M; i += 256) {
            float v = row[i];
            if (v > best) { best = v; barg = i; }
        }
        rmax[t] = best; rarg[t] = barg;
        __syncthreads();
        for (int s = 128; s > 0; s >>= 1) {
            if (t < s && rmax[t + s] > rmax[t]) { rmax[t] = rmax[t + s]; rarg[t] = rarg[t + s]; }
            __syncthreads();
        }
        if (t == 0) {
            vals[it] = rmax[0];
            idxs[it] = rarg[0];
            row[rarg[0]] = -INFINITY;     // exclude for next iteration
        }
        __syncthreads();
    }
    if (t == 0) {
        float vmax = vals[0];             // first selected is the max
        float s = 0.f;
        for (int j = 0; j < k; j++) { float e = expf(vals[j] - vmax); vals[j] = e; s += e; }
        float inv = 1.f / s;
        for (int j = 0; j < k; j++) {
            out_w[b * KMAX + j]   = vals[j] * inv;
            out_idx[b * KMAX + j] = idxs[j];
        }
    }
}

// ---------------- gather + weighted reduce + blend (the HBM-bound stage) ----------------
// grid = (BLK, B); 128 threads, each owns a float4 (512 floats per (b,l) row)
__global__ void gather_kernel(const float* __restrict__ MF, const float* __restrict__ enc,
                              const float* __restrict__ wscal, const int* __restrict__ kptr,
                              const int* __restrict__ idx, const float* __restrict__ w,
                              float* __restrict__ out) {
    int l = blockIdx.x;      // 0..63
    int b = blockIdx.y;      // 0..127
    __shared__ int   sidx[KMAX];
    __shared__ float sw[KMAX];
    int t = threadIdx.x;
    int k = *kptr;
    if (k > KMAX) k = KMAX;
    if (t < KMAX) { sidx[t] = (t < k) ? idx[b * KMAX + t] : 0;
                    sw[t]   = (t < k) ? w[b * KMAX + t]   : 0.f; }
    __syncthreads();

    int d = t * 4;
    float4 acc0 = make_float4(0.f, 0.f, 0.f, 0.f);
    float4 acc1 = make_float4(0.f, 0.f, 0.f, 0.f);

    if (k == 50) {
        // hot path: two independent unrolled halves -> two accumulator chains,
        // ~25 outstanding LDG.128 per wave (under the ~55/warp cap), no spill
        #pragma unroll
        for (int j = 0; j < 25; j++) {
            long roff = ((long)sidx[j] * BLK + l) * D + d;
            float4 v = *reinterpret_cast<const float4*>(MF + roff);
            float ww = sw[j];
            acc0.x += ww * v.x; acc0.y += ww * v.y; acc0.z += ww * v.z; acc0.w += ww * v.w;
        }
        #pragma unroll
        for (int j = 25; j < 50; j++) {
            long roff = ((long)sidx[j] * BLK + l) * D + d;
            float4 v = *reinterpret_cast<const float4*>(MF + roff);
            float ww = sw[j];
            acc1.x += ww * v.x; acc1.y += ww * v.y; acc1.z += ww * v.z; acc1.w += ww * v.w;
        }
    } else {
        for (int j = 0; j < k; j++) {
            long roff = ((long)sidx[j] * BLK + l) * D + d;
            float4 v = *reinterpret_cast<const float4*>(MF + roff);
            float ww = sw[j];
            acc0.x += ww * v.x; acc0.y += ww * v.y; acc0.z += ww * v.z; acc0.w += ww * v.w;
        }
    }
    float4 acc;
    acc.x = acc0.x + acc1.x; acc.y = acc0.y + acc1.y;
    acc.z = acc0.z + acc1.z; acc.w = acc0.w + acc1.w;

    float W = *wscal;
    float Wc = 1.f - W;
    long eoff = ((long)b * BLK + l) * D + d;
    float4 e = *reinterpret_cast<const float4*>(enc + eoff);
    float4 r;
    r.x = acc.x * W + e.x * Wc;
    r.y = acc.y * W + e.y * Wc;
    r.z = acc.z * W + e.z * Wc;
    r.w = acc.w * W + e.w * Wc;
    *reinterpret_cast<float4*>(out + eoff) = r;
}

extern "C" void kernel_launch(void* const* d_in, const int* in_sizes, int n_in,
                              void* d_out, int out_size) {
    const float* enc  = (const float*)d_in[0];   // [B, BLK, D]
    const float* q    = (const float*)d_in[1];   // [B, D]
    const float* mctx = (const float*)d_in[2];   // [M, D]
    const float* mf   = (const float*)d_in[3];   // [rows, D]
    const float* wsc  = (const float*)d_in[4];   // [1]
    const int*   kptr = (const int*)d_in[5];     // scalar k

    int M = in_sizes[2] / D;                     // 6304

    float *cosim, *qn, *mn, *wbuf; int *ibuf;
    cudaGetSymbolAddress((void**)&cosim, g_cos);
    cudaGetSymbolAddress((void**)&qn,    g_qn);
    cudaGetSymbolAddress((void**)&mn,    g_mn);
    cudaGetSymbolAddress((void**)&ibuf,  g_idx);
    cudaGetSymbolAddress((void**)&wbuf,  g_w);

    norm_kernel<<<B, 128>>>(q, qn, B);
    norm_kernel<<<M, 128>>>(mctx, mn, M);

    dim3 cgrid((M + 15) / 16, B / 16);
    cos_kernel<<<cgrid, dim3(16, 16)>>>(q, mctx, qn, mn, cosim, M);

    topk_kernel<<<B, 256, M * sizeof(float)>>>(cosim, kptr, M, ibuf, wbuf);

    gather_kernel<<<dim3(BLK, B), 128>>>(mf, enc, wsc, kptr, ibuf, wbuf, (float*)d_out);
}

// round 9
// speedup vs baseline: 1.4519x; 1.4519x over previous
#include <cuda_runtime.h>
#include <math.h>

// Problem constants (fixed by the dataset)
#define D     512
#define BLK   64
#define B     128
#define KMAX  64
#define MMAX  7168   // M = 6304 in dataset; margin for safety

// ---------------- scratch (no allocations allowed) ----------------
__device__ float g_cos[B * MMAX];     // cosine similarity [B, M]
__device__ float g_qn[B];             // query norms
__device__ float g_mn[MMAX];          // memory-context norms
__device__ int   g_idx[B * KMAX];     // top-k block indices
__device__ float g_w[B * KMAX];       // softmax weights

// ---------------- row L2 norms (clamped at eps) ----------------
__global__ void norm_kernel(const float* __restrict__ x, float* __restrict__ out, int nrows) {
    int row = blockIdx.x;
    if (row >= nrows) return;
    const float* p = x + (long)row * D;
    int t = threadIdx.x;
    float4 v = *reinterpret_cast<const float4*>(p + t * 4);
    float s = v.x * v.x + v.y * v.y + v.z * v.z + v.w * v.w;
    for (int off = 16; off > 0; off >>= 1) s += __shfl_down_sync(0xffffffffu, s, off);
    __shared__ float ws[4];
    if ((t & 31) == 0) ws[t >> 5] = s;
    __syncthreads();
    if (t == 0) {
        float tot = ws[0] + ws[1] + ws[2] + ws[3];
        out[row] = fmaxf(sqrtf(tot), 1e-8f);
    }
}

// ---------------- cos_sim GEMM: [B,D] x [M,D]^T -> [B,M] ----------------
// 64(m) x 64(b) tile per block, 256 threads, 4x4 register tile per thread.
// Smem stored k-major: inner loop = 2x LDS.128 + 16 FFMA, conflict-free.
__global__ void cos_kernel(const float* __restrict__ q, const float* __restrict__ m,
                           const float* __restrict__ qn, const float* __restrict__ mn,
                           float* __restrict__ out, int M) {
    __shared__ float Qs[16][68];   // [kk][batch row], pad to 68 (272B, 16B-aligned rows)
    __shared__ float Ms[16][68];   // [kk][mctx row]
    int t  = threadIdx.x;
    int tx = t & 15;               // mctx group (4 cols each)
    int ty = t >> 4;               // batch group (4 rows each)
    int mrow = blockIdx.x * 64;
    int brow = blockIdx.y * 64;

    int lr = t >> 2;               // 0..63 : row within tile to load
    int lk = (t & 3) * 4;          // 0,4,8,12 : kk base to load

    float acc[4][4];
    #pragma unroll
    for (int i = 0; i < 4; i++)
        #pragma unroll
        for (int j = 0; j < 4; j++) acc[i][j] = 0.f;

    for (int k0 = 0; k0 < D; k0 += 16) {
        // load Q tile (batch rows always in range: B=128 divisible by 64)
        float4 qv = *reinterpret_cast<const float4*>(q + (long)(brow + lr) * D + k0 + lk);
        Qs[lk + 0][lr] = qv.x; Qs[lk + 1][lr] = qv.y;
        Qs[lk + 2][lr] = qv.z; Qs[lk + 3][lr] = qv.w;
        // load M tile with bounds guard (M=6304 -> last tile half full)
        int mr = mrow + lr;
        float4 mv = make_float4(0.f, 0.f, 0.f, 0.f);
        if (mr < M) mv = *reinterpret_cast<const float4*>(m + (long)mr * D + k0 + lk);
        Ms[lk + 0][lr] = mv.x; Ms[lk + 1][lr] = mv.y;
        Ms[lk + 2][lr] = mv.z; Ms[lk + 3][lr] = mv.w;
        __syncthreads();
        #pragma unroll
        for (int kk = 0; kk < 16; kk++) {
            float4 a = *reinterpret_cast<const float4*>(&Qs[kk][ty * 4]);
            float4 bv = *reinterpret_cast<const float4*>(&Ms[kk][tx * 4]);
            acc[0][0] += a.x * bv.x; acc[0][1] += a.x * bv.y; acc[0][2] += a.x * bv.z; acc[0][3] += a.x * bv.w;
            acc[1][0] += a.y * bv.x; acc[1][1] += a.y * bv.y; acc[1][2] += a.y * bv.z; acc[1][3] += a.y * bv.w;
            acc[2][0] += a.z * bv.x; acc[2][1] += a.z * bv.y; acc[2][2] += a.z * bv.z; acc[2][3] += a.z * bv.w;
            acc[3][0] += a.w * bv.x; acc[3][1] += a.w * bv.y; acc[3][2] += a.w * bv.z; acc[3][3] += a.w * bv.w;
        }
        __syncthreads();
    }

    #pragma unroll
    for (int i = 0; i < 4; i++) {
        int gb = brow + ty * 4 + i;
        float qinv = 1.f / qn[gb];
        #pragma unroll
        for (int j = 0; j < 4; j++) {
            int gm = mrow + tx * 4 + j;
            if (gm < M)
                out[(long)gb * M + gm] = acc[i][j] * qinv / mn[gm];
        }
    }
}

// ---------------- top-k + softmax: one block per batch row ----------------
// Incremental argmax: per-thread register max over its 25 strided elements;
// per iteration only the owner of the removed element rescans.
__global__ void topk_kernel(const float* __restrict__ cosim, const int* __restrict__ kptr,
                            int M, int* __restrict__ out_idx, float* __restrict__ out_w) {
    extern __shared__ float row[];               // M floats
    __shared__ float wval[8];
    __shared__ int   warg[8];
    __shared__ int   bcast_arg;
    __shared__ float vals[KMAX];
    __shared__ int   idxs[KMAX];
    int b = blockIdx.x, t = threadIdx.x;
    int lane = t & 31, wid = t >> 5;
    int k = *kptr;
    if (k > KMAX) k = KMAX;

    for (int i = t; i < M; i += 256) row[i] = cosim[(long)b * M + i];
    __syncthreads();

    // one-time local scan (registers)
    float lmax = -INFINITY; int larg = 0;
    for (int i = t; i < M; i += 256) {
        float v = row[i];
        if (v > lmax) { lmax = v; larg = i; }
    }

    for (int it = 0; it < k; it++) {
        // warp argmax via shfl (no barriers)
        float v = lmax; int a = larg;
        #pragma unroll
        for (int off = 16; off > 0; off >>= 1) {
            float v2 = __shfl_down_sync(0xffffffffu, v, off);
            int   a2 = __shfl_down_sync(0xffffffffu, a, off);
            if (v2 > v) { v = v2; a = a2; }
        }
        if (lane == 0) { wval[wid] = v; warg[wid] = a; }
        __syncthreads();
        if (t == 0) {
            float bv = wval[0]; int ba = warg[0];
            #pragma unroll
            for (int j = 1; j < 8; j++)
                if (wval[j] > bv) { bv = wval[j]; ba = warg[j]; }
            vals[it] = bv; idxs[it] = ba;
            row[ba] = -INFINITY;          // remove winner
            bcast_arg = ba;
        }
        __syncthreads();
        int ba = bcast_arg;
        if ((ba & 255) == t) {            // owner rescans its 25 elements
            lmax = -INFINITY; larg = 0;
            for (int i = t; i < M; i += 256) {
                float vv = row[i];
                if (vv > lmax) { lmax = vv; larg = i; }
            }
        }
        // no extra barrier needed: others' registers unchanged; shfl syncs the warp
    }

    if (t == 0) {
        float vmax = vals[0];             // first selected is the max
        float s = 0.f;
        for (int j = 0; j < k; j++) { float e = expf(vals[j] - vmax); vals[j] = e; s += e; }
        float inv = 1.f / s;
        for (int j = 0; j < k; j++) {
            out_w[b * KMAX + j]   = vals[j] * inv;
            out_idx[b * KMAX + j] = idxs[j];
        }
    }
}

// ---------------- gather + weighted reduce + blend (the HBM-bound stage) ----------------
// grid = (BLK, B); 128 threads, each owns a float4 (512 floats per (b,l) row)
__global__ void gather_kernel(const float* __restrict__ MF, const float* __restrict__ enc,
                              const float* __restrict__ wscal, const int* __restrict__ kptr,
                              const int* __restrict__ idx, const float* __restrict__ w,
                              float* __restrict__ out) {
    int l = blockIdx.x;      // 0..63
    int b = blockIdx.y;      // 0..127
    __shared__ int   sidx[KMAX];
    __shared__ float sw[KMAX];
    int t = threadIdx.x;
    int k = *kptr;
    if (k > KMAX) k = KMAX;
    if (t < KMAX) { sidx[t] = (t < k) ? idx[b * KMAX + t] : 0;
                    sw[t]   = (t < k) ? w[b * KMAX + t]   : 0.f; }
    __syncthreads();

    int d = t * 4;
    float4 acc0 = make_float4(0.f, 0.f, 0.f, 0.f);
    float4 acc1 = make_float4(0.f, 0.f, 0.f, 0.f);

    if (k == 50) {
        #pragma unroll
        for (int j = 0; j < 25; j++) {
            long roff = ((long)sidx[j] * BLK + l) * D + d;
            float4 v = *reinterpret_cast<const float4*>(MF + roff);
            float ww = sw[j];
            acc0.x += ww * v.x; acc0.y += ww * v.y; acc0.z += ww * v.z; acc0.w += ww * v.w;
        }
        #pragma unroll
        for (int j = 25; j < 50; j++) {
            long roff = ((long)sidx[j] * BLK + l) * D + d;
            float4 v = *reinterpret_cast<const float4*>(MF + roff);
            float ww = sw[j];
            acc1.x += ww * v.x; acc1.y += ww * v.y; acc1.z += ww * v.z; acc1.w += ww * v.w;
        }
    } else {
        for (int j = 0; j < k; j++) {
            long roff = ((long)sidx[j] * BLK + l) * D + d;
            float4 v = *reinterpret_cast<const float4*>(MF + roff);
            float ww = sw[j];
            acc0.x += ww * v.x; acc0.y += ww * v.y; acc0.z += ww * v.z; acc0.w += ww * v.w;
        }
    }
    float4 acc;
    acc.x = acc0.x + acc1.x; acc.y = acc0.y + acc1.y;
    acc.z = acc0.z + acc1.z; acc.w = acc0.w + acc1.w;

    float W = *wscal;
    float Wc = 1.f - W;
    long eoff = ((long)b * BLK + l) * D + d;
    float4 e = *reinterpret_cast<const float4*>(enc + eoff);
    float4 r;
    r.x = acc.x * W + e.x * Wc;
    r.y = acc.y * W + e.y * Wc;
    r.z = acc.z * W + e.z * Wc;
    r.w = acc.w * W + e.w * Wc;
    *reinterpret_cast<float4*>(out + eoff) = r;
}

extern "C" void kernel_launch(void* const* d_in, const int* in_sizes, int n_in,
                              void* d_out, int out_size) {
    const float* enc  = (const float*)d_in[0];   // [B, BLK, D]
    const float* q    = (const float*)d_in[1];   // [B, D]
    const float* mctx = (const float*)d_in[2];   // [M, D]
    const float* mf   = (const float*)d_in[3];   // [rows, D]
    const float* wsc  = (const float*)d_in[4];   // [1]
    const int*   kptr = (const int*)d_in[5];     // scalar k

    int M = in_sizes[2] / D;                     // 6304

    float *cosim, *qn, *mn, *wbuf; int *ibuf;
    cudaGetSymbolAddress((void**)&cosim, g_cos);
    cudaGetSymbolAddress((void**)&qn,    g_qn);
    cudaGetSymbolAddress((void**)&mn,    g_mn);
    cudaGetSymbolAddress((void**)&ibuf,  g_idx);
    cudaGetSymbolAddress((void**)&wbuf,  g_w);

    norm_kernel<<<B, 128>>>(q, qn, B);
    norm_kernel<<<M, 128>>>(mctx, mn, M);

    dim3 cgrid((M + 63) / 64, B / 64);
    cos_kernel<<<cgrid, 256>>>(q, mctx, qn, mn, cosim, M);

    topk_kernel<<<B, 256, M * sizeof(float)>>>(cosim, kptr, M, ibuf, wbuf);

    gather_kernel<<<dim3(BLK, B), 128>>>(mf, enc, wsc, kptr, ibuf, wbuf, (float*)d_out);
}

// round 13
// speedup vs baseline: 1.5000x; 1.0332x over previous
#include <cuda_runtime.h>
#include <math.h>

// Problem constants (fixed by the dataset)
#define D     512
#define BLK   64
#define B     128
#define KMAX  64
#define MMAX  7168   // M = 6304 in dataset; margin for safety

// ---------------- scratch (no allocations allowed) ----------------
__device__ float g_cos[B * MMAX];     // cosine similarity [B, M]
__device__ float g_qn[B];             // query norms
__device__ float g_mn[MMAX];          // memory-context norms
__device__ int   g_idx[B * KMAX];     // top-k block indices
__device__ float g_w[B * KMAX];       // softmax weights

// ---------------- row L2 norms (clamped at eps) ----------------
__global__ void norm_kernel(const float* __restrict__ x, float* __restrict__ out, int nrows) {
    int row = blockIdx.x;
    if (row >= nrows) return;
    const float* p = x + (long)row * D;
    int t = threadIdx.x;
    float4 v = *reinterpret_cast<const float4*>(p + t * 4);
    float s = v.x * v.x + v.y * v.y + v.z * v.z + v.w * v.w;
    for (int off = 16; off > 0; off >>= 1) s += __shfl_down_sync(0xffffffffu, s, off);
    __shared__ float ws[4];
    if ((t & 31) == 0) ws[t >> 5] = s;
    __syncthreads();
    if (t == 0) {
        float tot = ws[0] + ws[1] + ws[2] + ws[3];
        out[row] = fmaxf(sqrtf(tot), 1e-8f);
    }
}

// ---------------- cos_sim GEMM: [B,D] x [M,D]^T -> [B,M] ----------------
// 64(m) x 64(b) tile per block, 256 threads, 4x4 register tile per thread.
__global__ void cos_kernel(const float* __restrict__ q, const float* __restrict__ m,
                           const float* __restrict__ qn, const float* __restrict__ mn,
                           float* __restrict__ out, int M) {
    __shared__ float Qs[16][68];
    __shared__ float Ms[16][68];
    int t  = threadIdx.x;
    int tx = t & 15;
    int ty = t >> 4;
    int mrow = blockIdx.x * 64;
    int brow = blockIdx.y * 64;

    int lr = t >> 2;
    int lk = (t & 3) * 4;

    float acc[4][4];
    #pragma unroll
    for (int i = 0; i < 4; i++)
        #pragma unroll
        for (int j = 0; j < 4; j++) acc[i][j] = 0.f;

    for (int k0 = 0; k0 < D; k0 += 16) {
        float4 qv = *reinterpret_cast<const float4*>(q + (long)(brow + lr) * D + k0 + lk);
        Qs[lk + 0][lr] = qv.x; Qs[lk + 1][lr] = qv.y;
        Qs[lk + 2][lr] = qv.z; Qs[lk + 3][lr] = qv.w;
        int mr = mrow + lr;
        float4 mv = make_float4(0.f, 0.f, 0.f, 0.f);
        if (mr < M) mv = *reinterpret_cast<const float4*>(m + (long)mr * D + k0 + lk);
        Ms[lk + 0][lr] = mv.x; Ms[lk + 1][lr] = mv.y;
        Ms[lk + 2][lr] = mv.z; Ms[lk + 3][lr] = mv.w;
        __syncthreads();
        #pragma unroll
        for (int kk = 0; kk < 16; kk++) {
            float4 a = *reinterpret_cast<const float4*>(&Qs[kk][ty * 4]);
            float4 bv = *reinterpret_cast<const float4*>(&Ms[kk][tx * 4]);
            acc[0][0] += a.x * bv.x; acc[0][1] += a.x * bv.y; acc[0][2] += a.x * bv.z; acc[0][3] += a.x * bv.w;
            acc[1][0] += a.y * bv.x; acc[1][1] += a.y * bv.y; acc[1][2] += a.y * bv.z; acc[1][3] += a.y * bv.w;
            acc[2][0] += a.z * bv.x; acc[2][1] += a.z * bv.y; acc[2][2] += a.z * bv.z; acc[2][3] += a.z * bv.w;
            acc[3][0] += a.w * bv.x; acc[3][1] += a.w * bv.y; acc[3][2] += a.w * bv.z; acc[3][3] += a.w * bv.w;
        }
        __syncthreads();
    }

    #pragma unroll
    for (int i = 0; i < 4; i++) {
        int gb = brow + ty * 4 + i;
        float qinv = 1.f / qn[gb];
        #pragma unroll
        for (int j = 0; j < 4; j++) {
            int gm = mrow + tx * 4 + j;
            if (gm < M)
                out[(long)gb * M + gm] = acc[i][j] * qinv / mn[gm];
        }
    }
}

// ---------------- top-k + softmax via RADIX SELECT ----------------
// One block (256 threads) per batch row. No serial k-iteration loop:
// 4 MSB-first 8-bit radix rounds find the exact 32-bit key of the k-th
// largest element; one deterministic prefix-sum pass collects the set.
// Softmax+weighted-sum downstream is permutation-invariant, so set order
// only needs to be DETERMINISTIC (it is: fixed thread-strided order).
__global__ void topk_kernel(const float* __restrict__ cosim, const int* __restrict__ kptr,
                            int M, int* __restrict__ out_idx, float* __restrict__ out_w) {
    extern __shared__ unsigned keys[];            // M order-preserving keys
    __shared__ unsigned hist[256];
    __shared__ unsigned wsum_gt[8], wsum_eq[8];
    __shared__ unsigned sh_prefix;
    __shared__ int      sh_kk, sh_totgt;
    __shared__ float sel_val[KMAX];
    __shared__ int   sel_idx[KMAX];

    int b = blockIdx.x, t = threadIdx.x;
    int lane = t & 31, wid = t >> 5;
    int k = *kptr;
    if (k > KMAX) k = KMAX;
    if (k < 1) k = 1;

    // load + fp32 -> order-preserving uint32
    for (int i = t; i < M; i += 256) {
        unsigned u = __float_as_uint(cosim[(long)b * M + i]);
        keys[i] = (u & 0x80000000u) ? ~u : (u | 0x80000000u);
    }
    __syncthreads();

    // 4 radix rounds, MSB first
    unsigned prefix = 0; int kk = k;
    #pragma unroll
    for (int round = 0; round < 4; round++) {
        int shift = 24 - 8 * round;
        hist[t] = 0;                      // blockDim == 256 covers all bins
        __syncthreads();
        for (int i = t; i < M; i += 256) {
            unsigned key = keys[i];
            bool match = (round == 0) || ((key >> (shift + 8)) == prefix);
            if (match) atomicAdd(&hist[(key >> shift) & 255u], 1u);
        }
        __syncthreads();
        if (t == 0) {
            unsigned cum = 0; int dsel = 0;
            for (int d = 255; d >= 0; d--) {
                cum += hist[d];
                if ((int)cum >= kk) { dsel = d; break; }
            }
            sh_kk = kk - (int)(cum - hist[dsel]);   // how many == this digit to take
            sh_prefix = (prefix << 8) | (unsigned)dsel;
        }
        __syncthreads();
        prefix = sh_prefix; kk = sh_kk;
    }
    unsigned T = prefix;                  // exact key of the k-th largest

    // deterministic collection: count, block-scan, place
    int c_gt = 0, c_eq = 0;
    for (int i = t; i < M; i += 256) {
        unsigned key = keys[i];
        c_gt += (key > T);
        c_eq += (key == T);
    }
    int s_gt = c_gt, s_eq = c_eq;
    #pragma unroll
    for (int off = 1; off < 32; off <<= 1) {
        int a = __shfl_up_sync(0xffffffffu, s_gt, off); if (lane >= off) s_gt += a;
        int e = __shfl_up_sync(0xffffffffu, s_eq, off); if (lane >= off) s_eq += e;
    }
    if (lane == 31) { wsum_gt[wid] = s_gt; wsum_eq[wid] = s_eq; }
    __syncthreads();
    if (t == 0) {
        unsigned rg = 0, re = 0;
        #pragma unroll
        for (int i2 = 0; i2 < 8; i2++) {
            unsigned tg = wsum_gt[i2]; wsum_gt[i2] = rg; rg += tg;
            unsigned te = wsum_eq[i2]; wsum_eq[i2] = re; re += te;
        }
        sh_totgt = (int)rg;               // count(key > T) == k - kk
    }
    __syncthreads();
    int base_gt = (int)wsum_gt[wid] + s_gt - c_gt;
    int base_eq = (int)wsum_eq[wid] + s_eq - c_eq;
    int totgt = sh_totgt;
    for (int i = t; i < M; i += 256) {
        unsigned key = keys[i];
        if (key > T) {
            int pos = base_gt++;
            unsigned u = (key & 0x80000000u) ? (key ^ 0x80000000u) : ~key;
            sel_val[pos] = __uint_as_float(u);
            sel_idx[pos] = i;
        } else if (key == T) {
            int pos = totgt + base_eq++;
            if (pos < k) {
                unsigned u = (key & 0x80000000u) ? (key ^ 0x80000000u) : ~key;
                sel_val[pos] = __uint_as_float(u);
                sel_idx[pos] = i;
            }
        }
    }
    __syncthreads();

    // softmax over the k selected (tiny; thread 0 serial)
    if (t == 0) {
        float vmax = -INFINITY;
        for (int j = 0; j < k; j++) vmax = fmaxf(vmax, sel_val[j]);
        float s = 0.f;
        for (int j = 0; j < k; j++) { float e = expf(sel_val[j] - vmax); sel_val[j] = e; s += e; }
        float inv = 1.f / s;
        for (int j = 0; j < k; j++) {
            out_w[b * KMAX + j]   = sel_val[j] * inv;
            out_idx[b * KMAX + j] = sel_idx[j];
        }
    }
}

// ---------------- gather + weighted reduce + blend (the HBM-bound stage) ----------------
// grid = (BLK, B); 128 threads, each owns a float4 (512 floats per (b,l) row)
__global__ void gather_kernel(const float* __restrict__ MF, const float* __restrict__ enc,
                              const float* __restrict__ wscal, const int* __restrict__ kptr,
                              const int* __restrict__ idx, const float* __restrict__ w,
                              float* __restrict__ out) {
    int l = blockIdx.x;      // 0..63
    int b = blockIdx.y;      // 0..127
    __shared__ int   sidx[KMAX];
    __shared__ float sw[KMAX];
    int t = threadIdx.x;
    int k = *kptr;
    if (k > KMAX) k = KMAX;
    if (t < KMAX) { sidx[t] = (t < k) ? idx[b * KMAX + t] : 0;
                    sw[t]   = (t < k) ? w[b * KMAX + t]   : 0.f; }
    __syncthreads();

    int d = t * 4;
    float4 acc0 = make_float4(0.f, 0.f, 0.f, 0.f);
    float4 acc1 = make_float4(0.f, 0.f, 0.f, 0.f);

    if (k == 50) {
        #pragma unroll
        for (int j = 0; j < 25; j++) {
            long roff = ((long)sidx[j] * BLK + l) * D + d;
            float4 v = *reinterpret_cast<const float4*>(MF + roff);
            float ww = sw[j];
            acc0.x += ww * v.x; acc0.y += ww * v.y; acc0.z += ww * v.z; acc0.w += ww * v.w;
        }
        #pragma unroll
        for (int j = 25; j < 50; j++) {
            long roff = ((long)sidx[j] * BLK + l) * D + d;
            float4 v = *reinterpret_cast<const float4*>(MF + roff);
            float ww = sw[j];
            acc1.x += ww * v.x; acc1.y += ww * v.y; acc1.z += ww * v.z; acc1.w += ww * v.w;
        }
    } else {
        for (int j = 0; j < k; j++) {
            long roff = ((long)sidx[j] * BLK + l) * D + d;
            float4 v = *reinterpret_cast<const float4*>(MF + roff);
            float ww = sw[j];
            acc0.x += ww * v.x; acc0.y += ww * v.y; acc0.z += ww * v.z; acc0.w += ww * v.w;
        }
    }
    float4 acc;
    acc.x = acc0.x + acc1.x; acc.y = acc0.y + acc1.y;
    acc.z = acc0.z + acc1.z; acc.w = acc0.w + acc1.w;

    float W = *wscal;
    float Wc = 1.f - W;
    long eoff = ((long)b * BLK + l) * D + d;
    float4 e = *reinterpret_cast<const float4*>(enc + eoff);
    float4 r;
    r.x = acc.x * W + e.x * Wc;
    r.y = acc.y * W + e.y * Wc;
    r.z = acc.z * W + e.z * Wc;
    r.w = acc.w * W + e.w * Wc;
    *reinterpret_cast<float4*>(out + eoff) = r;
}

extern "C" void kernel_launch(void* const* d_in, const int* in_sizes, int n_in,
                              void* d_out, int out_size) {
    const float* enc  = (const float*)d_in[0];   // [B, BLK, D]
    const float* q    = (const float*)d_in[1];   // [B, D]
    const float* mctx = (const float*)d_in[2];   // [M, D]
    const float* mf   = (const float*)d_in[3];   // [rows, D]
    const float* wsc  = (const float*)d_in[4];   // [1]
    const int*   kptr = (const int*)d_in[5];     // scalar k

    int M = in_sizes[2] / D;                     // 6304

    float *cosim, *qn, *mn, *wbuf; int *ibuf;
    cudaGetSymbolAddress((void**)&cosim, g_cos);
    cudaGetSymbolAddress((void**)&qn,    g_qn);
    cudaGetSymbolAddress((void**)&mn,    g_mn);
    cudaGetSymbolAddress((void**)&ibuf,  g_idx);
    cudaGetSymbolAddress((void**)&wbuf,  g_w);

    norm_kernel<<<B, 128>>>(q, qn, B);
    norm_kernel<<<M, 128>>>(mctx, mn, M);

    dim3 cgrid((M + 63) / 64, B / 64);
    cos_kernel<<<cgrid, 256>>>(q, mctx, qn, mn, cosim, M);

    topk_kernel<<<B, 256, M * sizeof(unsigned)>>>(cosim, kptr, M, ibuf, wbuf);

    gather_kernel<<<dim3(BLK, B), 128>>>(mf, enc, wsc, kptr, ibuf, wbuf, (float*)d_out);
}

// round 15
// speedup vs baseline: 1.6020x; 1.0680x over previous
#include <cuda_runtime.h>
#include <math.h>

// Problem constants (fixed by the dataset)
#define D     512
#define BLK   64
#define B     128
#define KMAX  64
#define MMAX  7168   // M = 6304 in dataset; margin for safety

// ---------------- scratch (no allocations allowed) ----------------
__device__ float g_cos[B * MMAX];     // cosine similarity [B, M]
__device__ float g_qn[B];             // query norms
__device__ float g_mn[MMAX];          // memory-context norms
__device__ int   g_idx[B * KMAX];     // top-k block indices
__device__ float g_w[B * KMAX];       // softmax weights

// ---------------- row L2 norms (clamped at eps) ----------------
__global__ void norm_kernel(const float* __restrict__ x, float* __restrict__ out, int nrows) {
    int row = blockIdx.x;
    if (row >= nrows) return;
    const float* p = x + (long)row * D;
    int t = threadIdx.x;
    float4 v = *reinterpret_cast<const float4*>(p + t * 4);
    float s = v.x * v.x + v.y * v.y + v.z * v.z + v.w * v.w;
    for (int off = 16; off > 0; off >>= 1) s += __shfl_down_sync(0xffffffffu, s, off);
    __shared__ float ws[4];
    if ((t & 31) == 0) ws[t >> 5] = s;
    __syncthreads();
    if (t == 0) {
        float tot = ws[0] + ws[1] + ws[2] + ws[3];
        out[row] = fmaxf(sqrtf(tot), 1e-8f);
    }
}

// ---------------- cos_sim GEMM: [B,D] x [M,D]^T -> [B,M] ----------------
// 64(m) x 64(b) tile per block, 256 threads, 4x4 register tile per thread.
__global__ void cos_kernel(const float* __restrict__ q, const float* __restrict__ m,
                           const float* __restrict__ qn, const float* __restrict__ mn,
                           float* __restrict__ out, int M) {
    __shared__ float Qs[16][68];
    __shared__ float Ms[16][68];
    int t  = threadIdx.x;
    int tx = t & 15;
    int ty = t >> 4;
    int mrow = blockIdx.x * 64;
    int brow = blockIdx.y * 64;

    int lr = t >> 2;
    int lk = (t & 3) * 4;

    float acc[4][4];
    #pragma unroll
    for (int i = 0; i < 4; i++)
        #pragma unroll
        for (int j = 0; j < 4; j++) acc[i][j] = 0.f;

    for (int k0 = 0; k0 < D; k0 += 16) {
        float4 qv = *reinterpret_cast<const float4*>(q + (long)(brow + lr) * D + k0 + lk);
        Qs[lk + 0][lr] = qv.x; Qs[lk + 1][lr] = qv.y;
        Qs[lk + 2][lr] = qv.z; Qs[lk + 3][lr] = qv.w;
        int mr = mrow + lr;
        float4 mv = make_float4(0.f, 0.f, 0.f, 0.f);
        if (mr < M) mv = *reinterpret_cast<const float4*>(m + (long)mr * D + k0 + lk);
        Ms[lk + 0][lr] = mv.x; Ms[lk + 1][lr] = mv.y;
        Ms[lk + 2][lr] = mv.z; Ms[lk + 3][lr] = mv.w;
        __syncthreads();
        #pragma unroll
        for (int kk = 0; kk < 16; kk++) {
            float4 a = *reinterpret_cast<const float4*>(&Qs[kk][ty * 4]);
            float4 bv = *reinterpret_cast<const float4*>(&Ms[kk][tx * 4]);
            acc[0][0] += a.x * bv.x; acc[0][1] += a.x * bv.y; acc[0][2] += a.x * bv.z; acc[0][3] += a.x * bv.w;
            acc[1][0] += a.y * bv.x; acc[1][1] += a.y * bv.y; acc[1][2] += a.y * bv.z; acc[1][3] += a.y * bv.w;
            acc[2][0] += a.z * bv.x; acc[2][1] += a.z * bv.y; acc[2][2] += a.z * bv.z; acc[2][3] += a.z * bv.w;
            acc[3][0] += a.w * bv.x; acc[3][1] += a.w * bv.y; acc[3][2] += a.w * bv.z; acc[3][3] += a.w * bv.w;
        }
        __syncthreads();
    }

    #pragma unroll
    for (int i = 0; i < 4; i++) {
        int gb = brow + ty * 4 + i;
        float qinv = 1.f / qn[gb];
        #pragma unroll
        for (int j = 0; j < 4; j++) {
            int gm = mrow + tx * 4 + j;
            if (gm < M)
                out[(long)gb * M + gm] = acc[i][j] * qinv / mn[gm];
        }
    }
}

// ---------------- top-k + softmax via RADIX SELECT (fully parallel) ----------------
// One block (256 threads) per batch row.
// vs. previous: per-warp histograms (bank-offset copies) remove round-0 smem
// atomic contention; parallel shfl suffix-scan replaces the 256-iteration
// serial thread-0 threshold scan; one-warp parallel softmax replaces the
// serial expf tail.
__global__ void topk_kernel(const float* __restrict__ cosim, const int* __restrict__ kptr,
                            int M, int* __restrict__ out_idx, float* __restrict__ out_w) {
    extern __shared__ unsigned keys[];            // M order-preserving keys
    __shared__ unsigned whist[8][257];            // per-warp histograms, bank-staggered
    __shared__ unsigned wscan[8];
    __shared__ unsigned wsum_gt[8], wsum_eq[8];
    __shared__ unsigned sh_prefix;
    __shared__ int      sh_kk, sh_totgt;
    __shared__ float sel_val[KMAX];
    __shared__ int   sel_idx[KMAX];

    int b = blockIdx.x, t = threadIdx.x;
    int lane = t & 31, wid = t >> 5;
    int k = *kptr;
    if (k > KMAX) k = KMAX;
    if (k < 1) k = 1;

    // load + fp32 -> order-preserving uint32
    for (int i = t; i < M; i += 256) {
        unsigned u = __float_as_uint(cosim[(long)b * M + i]);
        keys[i] = (u & 0x80000000u) ? ~u : (u | 0x80000000u);
    }
    __syncthreads();

    // 4 radix rounds, MSB first
    unsigned prefix = 0; int kk = k;
    #pragma unroll
    for (int round = 0; round < 4; round++) {
        int shift = 24 - 8 * round;
        // zero per-warp histograms
        for (int i = t; i < 8 * 257; i += 256) (&whist[0][0])[i] = 0;
        __syncthreads();
        // sweep: each warp accumulates into its own bank-staggered copy
        for (int i = t; i < M; i += 256) {
            unsigned key = keys[i];
            bool match = (round == 0) || ((key >> (shift + 8)) == prefix);
            if (match) atomicAdd(&whist[wid][(key >> shift) & 255u], 1u);
        }
        __syncthreads();
        // thread t owns DESCENDING-rank bin d = 255 - t; reduce 8 copies
        int d = 255 - t;
        unsigned hv = 0;
        #pragma unroll
        for (int w = 0; w < 8; w++) hv += whist[w][d];
        // inclusive scan over t (= suffix sum over bins from the top down)
        unsigned S = hv;
        #pragma unroll
        for (int off = 1; off < 32; off <<= 1) {
            unsigned x = __shfl_up_sync(0xffffffffu, S, off);
            if (lane >= off) S += x;
        }
        if (lane == 31) wscan[wid] = S;
        __syncthreads();
        unsigned base = 0;
        #pragma unroll
        for (int w = 0; w < 8; w++) base += (w < wid) ? wscan[w] : 0u;
        S += base;
        // unique boundary thread: cumulative count first reaches kk at this bin
        if (S >= (unsigned)kk && (S - hv) < (unsigned)kk) {
            sh_prefix = (prefix << 8) | (unsigned)d;
            sh_kk = kk - (int)(S - hv);
        }
        __syncthreads();
        prefix = sh_prefix; kk = sh_kk;
    }
    unsigned T = prefix;                  // exact key of the k-th largest

    // deterministic collection: count, block-scan, place
    int c_gt = 0, c_eq = 0;
    for (int i = t; i < M; i += 256) {
        unsigned key = keys[i];
        c_gt += (key > T);
        c_eq += (key == T);
    }
    int s_gt = c_gt, s_eq = c_eq;
    #pragma unroll
    for (int off = 1; off < 32; off <<= 1) {
        int a = __shfl_up_sync(0xffffffffu, s_gt, off); if (lane >= off) s_gt += a;
        int e = __shfl_up_sync(0xffffffffu, s_eq, off); if (lane >= off) s_eq += e;
    }
    if (lane == 31) { wsum_gt[wid] = s_gt; wsum_eq[wid] = s_eq; }
    __syncthreads();
    if (t == 0) {
        unsigned rg = 0, re = 0;
        #pragma unroll
        for (int i2 = 0; i2 < 8; i2++) {
            unsigned tg = wsum_gt[i2]; wsum_gt[i2] = rg; rg += tg;
            unsigned te = wsum_eq[i2]; wsum_eq[i2] = re; re += te;
        }
        sh_totgt = (int)rg;               // count(key > T) == k - kk
    }
    __syncthreads();
    int base_gt = (int)wsum_gt[wid] + s_gt - c_gt;
    int base_eq = (int)wsum_eq[wid] + s_eq - c_eq;
    int totgt = sh_totgt;
    for (int i = t; i < M; i += 256) {
        unsigned key = keys[i];
        if (key > T) {
            int pos = base_gt++;
            unsigned u = (key & 0x80000000u) ? (key ^ 0x80000000u) : ~key;
            sel_val[pos] = __uint_as_float(u);
            sel_idx[pos] = i;
        } else if (key == T) {
            int pos = totgt + base_eq++;
            if (pos < k) {
                unsigned u = (key & 0x80000000u) ? (key ^ 0x80000000u) : ~key;
                sel_val[pos] = __uint_as_float(u);
                sel_idx[pos] = i;
            }
        }
    }
    __syncthreads();

    // warp-parallel softmax over the k selected (warp 0, 2 elems/lane)
    if (wid == 0) {
        float v0 = (lane      < k) ? sel_val[lane]      : -INFINITY;
        float v1 = (lane + 32 < k) ? sel_val[lane + 32] : -INFINITY;
        float vm = fmaxf(v0, v1);
        #pragma unroll
        for (int off = 16; off > 0; off >>= 1)
            vm = fmaxf(vm, __shfl_xor_sync(0xffffffffu, vm, off));
        float e0 = (lane      < k) ? expf(v0 - vm) : 0.f;
        float e1 = (lane + 32 < k) ? expf(v1 - vm) : 0.f;
        float s = e0 + e1;
        #pragma unroll
        for (int off = 16; off > 0; off >>= 1)
            s += __shfl_xor_sync(0xffffffffu, s, off);
        float inv = 1.f / s;
        if (lane < k) {
            out_w[b * KMAX + lane]   = e0 * inv;
            out_idx[b * KMAX + lane] = sel_idx[lane];
        }
        if (lane + 32 < k) {
            out_w[b * KMAX + lane + 32]   = e1 * inv;
            out_idx[b * KMAX + lane + 32] = sel_idx[lane + 32];
        }
    }
}

// ---------------- gather + weighted reduce + blend (the HBM-bound stage) ----------------
// grid = (BLK, B); 128 threads, each owns a float4 (512 floats per (b,l) row)
__global__ void gather_kernel(const float* __restrict__ MF, const float* __restrict__ enc,
                              const float* __restrict__ wscal, const int* __restrict__ kptr,
                              const int* __restrict__ idx, const float* __restrict__ w,
                              float* __restrict__ out) {
    int l = blockIdx.x;      // 0..63
    int b = blockIdx.y;      // 0..127
    __shared__ int   sidx[KMAX];
    __shared__ float sw[KMAX];
    int t = threadIdx.x;
    int k = *kptr;
    if (k > KMAX) k = KMAX;
    if (t < KMAX) { sidx[t] = (t < k) ? idx[b * KMAX + t] : 0;
                    sw[t]   = (t < k) ? w[b * KMAX + t]   : 0.f; }
    __syncthreads();

    int d = t * 4;
    float4 acc0 = make_float4(0.f, 0.f, 0.f, 0.f);
    float4 acc1 = make_float4(0.f, 0.f, 0.f, 0.f);

    if (k == 50) {
        #pragma unroll
        for (int j = 0; j < 25; j++) {
            long roff = ((long)sidx[j] * BLK + l) * D + d;
            float4 v = *reinterpret_cast<const float4*>(MF + roff);
            float ww = sw[j];
            acc0.x += ww * v.x; acc0.y += ww * v.y; acc0.z += ww * v.z; acc0.w += ww * v.w;
        }
        #pragma unroll
        for (int j = 25; j < 50; j++) {
            long roff = ((long)sidx[j] * BLK + l) * D + d;
            float4 v = *reinterpret_cast<const float4*>(MF + roff);
            float ww = sw[j];
            acc1.x += ww * v.x; acc1.y += ww * v.y; acc1.z += ww * v.z; acc1.w += ww * v.w;
        }
    } else {
        for (int j = 0; j < k; j++) {
            long roff = ((long)sidx[j] * BLK + l) * D + d;
            float4 v = *reinterpret_cast<const float4*>(MF + roff);
            float ww = sw[j];
            acc0.x += ww * v.x; acc0.y += ww * v.y; acc0.z += ww * v.z; acc0.w += ww * v.w;
        }
    }
    float4 acc;
    acc.x = acc0.x + acc1.x; acc.y = acc0.y + acc1.y;
    acc.z = acc0.z + acc1.z; acc.w = acc0.w + acc1.w;

    float W = *wscal;
    float Wc = 1.f - W;
    long eoff = ((long)b * BLK + l) * D + d;
    float4 e = *reinterpret_cast<const float4*>(enc + eoff);
    float4 r;
    r.x = acc.x * W + e.x * Wc;
    r.y = acc.y * W + e.y * Wc;
    r.z = acc.z * W + e.z * Wc;
    r.w = acc.w * W + e.w * Wc;
    *reinterpret_cast<float4*>(out + eoff) = r;
}

extern "C" void kernel_launch(void* const* d_in, const int* in_sizes, int n_in,
                              void* d_out, int out_size) {
    const float* enc  = (const float*)d_in[0];   // [B, BLK, D]
    const float* q    = (const float*)d_in[1];   // [B, D]
    const float* mctx = (const float*)d_in[2];   // [M, D]
    const float* mf   = (const float*)d_in[3];   // [rows, D]
    const float* wsc  = (const float*)d_in[4];   // [1]
    const int*   kptr = (const int*)d_in[5];     // scalar k

    int M = in_sizes[2] / D;                     // 6304

    float *cosim, *qn, *mn, *wbuf; int *ibuf;
    cudaGetSymbolAddress((void**)&cosim, g_cos);
    cudaGetSymbolAddress((void**)&qn,    g_qn);
    cudaGetSymbolAddress((void**)&mn,    g_mn);
    cudaGetSymbolAddress((void**)&ibuf,  g_idx);
    cudaGetSymbolAddress((void**)&wbuf,  g_w);

    norm_kernel<<<B, 128>>>(q, qn, B);
    norm_kernel<<<M, 128>>>(mctx, mn, M);

    dim3 cgrid((M + 63) / 64, B / 64);
    cos_kernel<<<cgrid, 256>>>(q, mctx, qn, mn, cosim, M);

    topk_kernel<<<B, 256, M * sizeof(unsigned)>>>(cosim, kptr, M, ibuf, wbuf);

    gather_kernel<<<dim3(BLK, B), 128>>>(mf, enc, wsc, kptr, ibuf, wbuf, (float*)d_out);
}